// round 13
// baseline (speedup 1.0000x reference)
#include <cuda_runtime.h>
#include <cuda_fp16.h>
#include <cstdint>

#define D_MODEL 1024
#define NHEAD   16
#define DKH     64
#define BATCH   4
#define SEQ     2048
#define MTOT    (BATCH*SEQ)   // 8192

// Scratch: projected Q/K/V + attention concat in fp16, all [b][s][h*d].
__device__ __half g_Qp[(size_t)MTOT * D_MODEL];
__device__ __half g_Kp[(size_t)MTOT * D_MODEL];
__device__ __half g_Vp[(size_t)MTOT * D_MODEL];
__device__ __half g_Ct[(size_t)MTOT * D_MODEL];
// fp16-RN pre-rounded copies (cp.async path cannot convert)
__device__ __half g_rQ[(size_t)MTOT * D_MODEL];
__device__ __half g_rK[(size_t)MTOT * D_MODEL];
__device__ __half g_rV[(size_t)MTOT * D_MODEL];
__device__ __half g_rWq[(size_t)D_MODEL * D_MODEL];
__device__ __half g_rWk[(size_t)D_MODEL * D_MODEL];
__device__ __half g_rWv[(size_t)D_MODEL * D_MODEL];
__device__ __half g_rWo[(size_t)D_MODEL * D_MODEL];

// ---------------- PTX helpers ----------------
__device__ __forceinline__ float ex2f(float x) {
    float y;
    asm("ex2.approx.f32 %0, %1;" : "=f"(y) : "f"(x));
    return y;
}
__device__ __forceinline__ uint32_t smem_u32(const void* p) {
    uint32_t a;
    asm("{ .reg .u64 t; cvta.to.shared.u64 t, %1; cvt.u32.u64 %0, t; }" : "=r"(a) : "l"(p));
    return a;
}
__device__ __forceinline__ void mma_f16(float c[4], const uint32_t a[4],
                                        uint32_t b0, uint32_t b1) {
    asm volatile(
        "mma.sync.aligned.m16n8k16.row.col.f32.f16.f16.f32 "
        "{%0,%1,%2,%3}, {%4,%5,%6,%7}, {%8,%9}, {%0,%1,%2,%3};"
        : "+f"(c[0]), "+f"(c[1]), "+f"(c[2]), "+f"(c[3])
        : "r"(a[0]), "r"(a[1]), "r"(a[2]), "r"(a[3]), "r"(b0), "r"(b1));
}
#define LDSM_X4(r0,r1,r2,r3,addr) \
    asm volatile("ldmatrix.sync.aligned.m8n8.x4.shared.b16 {%0,%1,%2,%3}, [%4];" \
        : "=r"(r0),"=r"(r1),"=r"(r2),"=r"(r3) : "r"(addr))
#define LDSM_X4_T(r0,r1,r2,r3,addr) \
    asm volatile("ldmatrix.sync.aligned.m8n8.x4.trans.shared.b16 {%0,%1,%2,%3}, [%4];" \
        : "=r"(r0),"=r"(r1),"=r"(r2),"=r"(r3) : "r"(addr))
#define CP16(sa, ga)  asm volatile("cp.async.cg.shared.global [%0], [%1], 16;" :: "r"(sa), "l"(ga))
#define CP_COMMIT()   asm volatile("cp.async.commit_group;" ::: "memory")
#define CP_WAIT(n)    asm volatile("cp.async.wait_group %0;" :: "n"(n) : "memory")

// ---------------- fused fp16-RN rounding pass ----------------
#define NB4 (MTOT * D_MODEL / 4)
#define NW4 (D_MODEL * D_MODEL / 4)
#define NTOT4 (3 * NB4 + 4 * NW4)

__global__ void round_all(
    const float* __restrict__ Qi, const float* __restrict__ Ki, const float* __restrict__ Vi,
    const float* __restrict__ Wq, const float* __restrict__ Wk,
    const float* __restrict__ Wv, const float* __restrict__ Wo,
    __half* __restrict__ rQ, __half* __restrict__ rK, __half* __restrict__ rV,
    __half* __restrict__ rWq, __half* __restrict__ rWk, __half* __restrict__ rWv,
    __half* __restrict__ rWo)
{
    const int i = blockIdx.x * blockDim.x + threadIdx.x;
    if (i >= NTOT4) return;
    const float4* src;
    __half* dst;
    int off;
    if (i < 3 * NB4) {
        const int seg = i / NB4;
        off = i - seg * NB4;
        src = (const float4*)(seg == 0 ? Qi : seg == 1 ? Ki : Vi);
        dst = seg == 0 ? rQ : seg == 1 ? rK : rV;
    } else {
        const int j = i - 3 * NB4;
        const int seg = j / NW4;
        off = j - seg * NW4;
        src = (const float4*)(seg == 0 ? Wq : seg == 1 ? Wk : seg == 2 ? Wv : Wo);
        dst = seg == 0 ? rWq : seg == 1 ? rWk : seg == 2 ? rWv : rWo;
    }
    float4 v = src[off];
    half2 h0 = __floats2half2_rn(v.x, v.y);
    half2 h1 = __floats2half2_rn(v.z, v.w);
    uint2 u;
    u.x = *(uint32_t*)&h0;
    u.y = *(uint32_t*)&h1;
    *(uint2*)(dst + 4 * (size_t)off) = u;
}

// ======================================================================
// fp16 GEMM core (NT): C[8192,1024] = A * B^T. 128x128 tile, BK=64
// (128B rows), 3-stage cp.async, ldmatrix, m16n8k16 MMA.
// mode 0: raw fp32 out. mode 1: fp16 out.
// ======================================================================
#define GEMM_SMEM (3 * 32768)

__device__ __forceinline__ void gemm_body(
    const __half* __restrict__ A, const __half* __restrict__ B,
    void* __restrict__ Cv, int mode, char* sm)
{
    const uint32_t sbase = smem_u32(sm);
    const int tid = threadIdx.x, lane = tid & 31, wid = tid >> 5;
    const int wm = (wid & 1) * 64, wn = (wid >> 1) * 32;
    const int m0 = blockIdx.y * 128, n0 = blockIdx.x * 128;

    float c[4][4][4];
    #pragma unroll
    for (int i = 0; i < 4; i++)
        #pragma unroll
        for (int j = 0; j < 4; j++)
            #pragma unroll
            for (int r = 0; r < 4; r++) c[i][j][r] = 0.f;

    auto issue = [&](int kt, int buf) {
        #pragma unroll
        for (int i = 0; i < 4; i++) {
            const int id = tid + 256 * i;
            const int row = id >> 3, cx = id & 7;
            const uint32_t off = row * 128 + (((uint32_t)(cx ^ (row & 7))) << 4);
            const __half* ga = A + (size_t)(m0 + row) * 1024 + kt * 64 + cx * 8;
            const __half* gb = B + (size_t)(n0 + row) * 1024 + kt * 64 + cx * 8;
            CP16(sbase + buf * 32768 + off, ga);
            CP16(sbase + buf * 32768 + 16384 + off, gb);
        }
        CP_COMMIT();
    };

    issue(0, 0);
    issue(1, 1);

    const int NKT = 16;
    for (int kt = 0; kt < NKT; kt++) {
        if (kt + 1 < NKT) { CP_WAIT(1); } else { CP_WAIT(0); }
        __syncthreads();
        if (kt + 2 < NKT) issue(kt + 2, (kt + 2) % 3);

        const uint32_t abase = sbase + (kt % 3) * 32768;
        const uint32_t bbase = abase + 16384;
        #pragma unroll
        for (int ks = 0; ks < 4; ks++) {
            uint32_t a[4][4];
            #pragma unroll
            for (int mt = 0; mt < 4; mt++) {
                const int row = wm + mt * 16 + (lane & 7) + ((lane >> 3) & 1) * 8;
                const int ch  = 2 * ks + (lane >> 4);
                const uint32_t ad = abase + row * 128 + (((uint32_t)(ch ^ (row & 7))) << 4);
                LDSM_X4(a[mt][0], a[mt][1], a[mt][2], a[mt][3], ad);
            }
            #pragma unroll
            for (int p = 0; p < 2; p++) {
                const int row = wn + p * 16 + ((lane >> 4) & 1) * 8 + (lane & 7);
                const int ch  = 2 * ks + ((lane >> 3) & 1);
                const uint32_t bd = bbase + row * 128 + (((uint32_t)(ch ^ (row & 7))) << 4);
                uint32_t b0, b1, b2, b3;
                LDSM_X4(b0, b1, b2, b3, bd);
                #pragma unroll
                for (int mt = 0; mt < 4; mt++) {
                    mma_f16(c[mt][2*p],     a[mt], b0, b1);
                    mma_f16(c[mt][2*p + 1], a[mt], b2, b3);
                }
            }
        }
    }

    const int mbase = m0 + wm + (lane >> 2);
    const int nbase = n0 + wn + (lane & 3) * 2;
    if (mode == 1) {
        __half* Ch = (__half*)Cv;
        #pragma unroll
        for (int mt = 0; mt < 4; mt++) {
            #pragma unroll
            for (int nt = 0; nt < 4; nt++) {
                *(half2*)(Ch + (size_t)(mbase + mt*16)     * 1024 + nbase + nt*8) =
                    __floats2half2_rn(c[mt][nt][0], c[mt][nt][1]);
                *(half2*)(Ch + (size_t)(mbase + mt*16 + 8) * 1024 + nbase + nt*8) =
                    __floats2half2_rn(c[mt][nt][2], c[mt][nt][3]);
            }
        }
    } else {
        float* C = (float*)Cv;
        #pragma unroll
        for (int mt = 0; mt < 4; mt++) {
            #pragma unroll
            for (int nt = 0; nt < 4; nt++) {
                float* p0 = C + (size_t)(mbase + mt*16)     * 1024 + nbase + nt*8;
                float* p1 = C + (size_t)(mbase + mt*16 + 8) * 1024 + nbase + nt*8;
                *(float2*)p0 = make_float2(c[mt][nt][0], c[mt][nt][1]);
                *(float2*)p1 = make_float2(c[mt][nt][2], c[mt][nt][3]);
            }
        }
    }
}

// Fused QKV projections: blockIdx.z selects (A, B, C).
__global__ __launch_bounds__(256, 2) void gemm_qkv(
    const __half* __restrict__ A0, const __half* __restrict__ A1, const __half* __restrict__ A2,
    const __half* __restrict__ B0, const __half* __restrict__ B1, const __half* __restrict__ B2,
    __half* __restrict__ C0, __half* __restrict__ C1, __half* __restrict__ C2)
{
    extern __shared__ char sm[];
    const int z = blockIdx.z;
    const __half* A = z == 0 ? A0 : z == 1 ? A1 : A2;
    const __half* B = z == 0 ? B0 : z == 1 ? B1 : B2;
    __half* C       = z == 0 ? C0 : z == 1 ? C1 : C2;
    gemm_body(A, B, C, 1, sm);
}

__global__ __launch_bounds__(256, 2) void gemm_tc(
    const __half* __restrict__ A, const __half* __restrict__ B,
    float* __restrict__ C, int mode)
{
    extern __shared__ char sm[];
    gemm_body(A, B, C, mode, sm);
}

// ======================================================================
// Flash attention v9 = R11 geometry (BQ=128, 8 warps, 2 CTAs/SM) +
// bit-exact ballot-uniform rescale skip. fp16 m16n8k16 MMA, fp32
// softmax/accum. K/V double-buffered via cp.async, end-of-iter prefetch.
// Smem: K0 8K | K1 8K | V0 8K | V1 8K | PQ 16K = 48 KB.
// ======================================================================
#define KOFF(buf)  ((buf) * 8192)
#define VOFF(buf)  (16384 + (buf) * 8192)
#define POFF       32768
#define FLASH_SMEM 49152
#define SM_SCALE_LOG2E 0.1803368801111204f   // 0.125 * log2(e)

__global__ __launch_bounds__(256, 2) void flash_tc(
    const __half* __restrict__ Qp, const __half* __restrict__ Kp,
    const __half* __restrict__ Vp, __half* __restrict__ Op)
{
    extern __shared__ char fsc[];
    const uint32_t sb = smem_u32(fsc);
    const int tid = threadIdx.x, lane = tid & 31, w = tid >> 5;
    const int b = blockIdx.z, h = blockIdx.y;
    const int q0 = blockIdx.x * 128;

    const __half* Qg = Qp + ((size_t)b * SEQ + q0) * D_MODEL + h * DKH;
    const __half* Kg = Kp + (size_t)b * SEQ * D_MODEL + h * DKH;
    const __half* Vg = Vp + (size_t)b * SEQ * D_MODEL + h * DKH;

    auto issueKV = [&](int kt, int buf) {
        #pragma unroll
        for (int i = 0; i < 2; i++) {
            const int id = tid + 256 * i;
            const int row = id >> 3, cx = id & 7;
            const uint32_t off = row * 128 + (((uint32_t)(cx ^ (row & 7))) << 4);
            CP16(sb + KOFF(buf) + off, Kg + (size_t)(kt * 64 + row) * D_MODEL + cx * 8);
            CP16(sb + VOFF(buf) + off, Vg + (size_t)(kt * 64 + row) * D_MODEL + cx * 8);
        }
        CP_COMMIT();
    };

    #pragma unroll
    for (int i = 0; i < 4; i++) {
        const int id = tid + 256 * i;
        const int row = id >> 3, cx = id & 7;
        const uint32_t off = row * 128 + (((uint32_t)(cx ^ (row & 7))) << 4);
        CP16(sb + POFF + off, Qg + (size_t)row * D_MODEL + cx * 8);
    }
    issueKV(0, 0);
    issueKV(1, 1);

    float o[8][4];
    #pragma unroll
    for (int nt = 0; nt < 8; nt++)
        #pragma unroll
        for (int j = 0; j < 4; j++) o[nt][j] = 0.f;
    float m0r = -1e30f, m1r = -1e30f, l0r = 0.f, l1r = 0.f;
    uint32_t qf[4][4];

    const int arow = w * 16 + (lane & 7) + ((lane >> 3) & 1) * 8;
    const uint32_t arow_off = (uint32_t)arow * 128;
    const int asw = arow & 7;
    const int achsel = lane >> 4;

    const int NKT = SEQ / 64;
    for (int kt = 0; kt < NKT; kt++) {
        if (kt + 1 < NKT) { CP_WAIT(1); } else { CP_WAIT(0); }
        __syncthreads();

        if (kt == 0) {
            #pragma unroll
            for (int ks = 0; ks < 4; ks++) {
                const uint32_t ad = sb + POFF + arow_off +
                    (((uint32_t)((2 * ks + achsel) ^ asw)) << 4);
                LDSM_X4(qf[ks][0], qf[ks][1], qf[ks][2], qf[ks][3], ad);
            }
        }

        const int buf = kt & 1;
        const uint32_t Kb = sb + KOFF(buf);
        const uint32_t Vb = sb + VOFF(buf);

        // ---- S = Q K^T ----
        float sf[8][4];
        #pragma unroll
        for (int nt = 0; nt < 8; nt++)
            #pragma unroll
            for (int j = 0; j < 4; j++) sf[nt][j] = 0.f;

        #pragma unroll
        for (int ks = 0; ks < 4; ks++) {
            #pragma unroll
            for (int pp = 0; pp < 4; pp++) {
                const int krow = (2 * pp + ((lane >> 4) & 1)) * 8 + (lane & 7);
                const int kch  = 2 * ks + ((lane >> 3) & 1);
                const uint32_t bd = Kb + (uint32_t)krow * 128 +
                    (((uint32_t)(kch ^ (krow & 7))) << 4);
                uint32_t b0, b1, b2, b3;
                LDSM_X4(b0, b1, b2, b3, bd);
                mma_f16(sf[2*pp],     qf[ks], b0, b1);
                mma_f16(sf[2*pp + 1], qf[ks], b2, b3);
            }
        }

        // ---- online softmax ----
        float mn0 = m0r, mn1 = m1r;
        #pragma unroll
        for (int nt = 0; nt < 8; nt++) {
            mn0 = fmaxf(mn0, fmaxf(sf[nt][0], sf[nt][1]));
            mn1 = fmaxf(mn1, fmaxf(sf[nt][2], sf[nt][3]));
        }
        mn0 = fmaxf(mn0, __shfl_xor_sync(0xffffffffu, mn0, 1));
        mn0 = fmaxf(mn0, __shfl_xor_sync(0xffffffffu, mn0, 2));
        mn1 = fmaxf(mn1, __shfl_xor_sync(0xffffffffu, mn1, 1));
        mn1 = fmaxf(mn1, __shfl_xor_sync(0xffffffffu, mn1, 2));

        const bool changed = (mn0 != m0r) || (mn1 != m1r);
        const float nc0 = -mn0 * SM_SCALE_LOG2E;
        const float nc1 = -mn1 * SM_SCALE_LOG2E;

        float rs0 = 0.f, rs1 = 0.f;
        #pragma unroll
        for (int nt = 0; nt < 8; nt++) {
            sf[nt][0] = ex2f(fmaf(sf[nt][0], SM_SCALE_LOG2E, nc0));
            sf[nt][1] = ex2f(fmaf(sf[nt][1], SM_SCALE_LOG2E, nc0));
            sf[nt][2] = ex2f(fmaf(sf[nt][2], SM_SCALE_LOG2E, nc1));
            sf[nt][3] = ex2f(fmaf(sf[nt][3], SM_SCALE_LOG2E, nc1));
            rs0 += sf[nt][0] + sf[nt][1];
            rs1 += sf[nt][2] + sf[nt][3];
        }
        rs0 += __shfl_xor_sync(0xffffffffu, rs0, 1);
        rs0 += __shfl_xor_sync(0xffffffffu, rs0, 2);
        rs1 += __shfl_xor_sync(0xffffffffu, rs1, 1);
        rs1 += __shfl_xor_sync(0xffffffffu, rs1, 2);

        if (__ballot_sync(0xffffffffu, changed)) {
            const float corr0 = ex2f((m0r - mn0) * SM_SCALE_LOG2E);
            const float corr1 = ex2f((m1r - mn1) * SM_SCALE_LOG2E);
            m0r = mn0; m1r = mn1;
            l0r = l0r * corr0 + rs0;
            l1r = l1r * corr1 + rs1;
            #pragma unroll
            for (int nt = 0; nt < 8; nt++) {
                o[nt][0] *= corr0; o[nt][1] *= corr0;
                o[nt][2] *= corr1; o[nt][3] *= corr1;
            }
        } else {
            // no row max changed in this warp: corr == 1 exactly
            l0r += rs0;
            l1r += rs1;
        }

        // ---- P (fp16) -> PQ region, warp-private rows ----
        {
            const int r0 = w * 16 + (lane >> 2);
            const int r1 = r0 + 8;
            const uint32_t cc4 = (uint32_t)(lane & 3) * 4;
            #pragma unroll
            for (int nt = 0; nt < 8; nt++) {
                *(half2*)(fsc + POFF + r0 * 128 +
                          (((uint32_t)(nt ^ (r0 & 7))) << 4) + cc4) =
                    __floats2half2_rn(sf[nt][0], sf[nt][1]);
                *(half2*)(fsc + POFF + r1 * 128 +
                          (((uint32_t)(nt ^ (r1 & 7))) << 4) + cc4) =
                    __floats2half2_rn(sf[nt][2], sf[nt][3]);
            }
        }
        __syncwarp();

        // ---- O += P V ----
        #pragma unroll
        for (int ks = 0; ks < 4; ks++) {
            uint32_t pf[4];
            const uint32_t pd = sb + POFF + arow_off +
                (((uint32_t)((2 * ks + achsel) ^ asw)) << 4);
            LDSM_X4(pf[0], pf[1], pf[2], pf[3], pd);
            #pragma unroll
            for (int pp = 0; pp < 4; pp++) {
                const int vrow = ks * 16 + (lane & 7) + ((lane >> 3) & 1) * 8;
                const int vch  = 2 * pp + ((lane >> 4) & 1);
                const uint32_t vd = Vb + (uint32_t)vrow * 128 +
                    (((uint32_t)(vch ^ (vrow & 7))) << 4);
                uint32_t b0, b1, b2, b3;
                LDSM_X4_T(b0, b1, b2, b3, vd);
                mma_f16(o[2*pp],     pf, b0, b1);
                mma_f16(o[2*pp + 1], pf, b2, b3);
            }
        }

        if (kt + 2 < NKT) {
            __syncthreads();
            issueKV(kt + 2, buf);
        }
    }

    // epilogue: normalize, fp16-round, write Ct (fp16)
    const float inv0 = 1.f / l0r, inv1 = 1.f / l1r;
    const int row0 = q0 + w * 16 + (lane >> 2);
    const int col  = h * DKH + (lane & 3) * 2;
    __half* Ob = Op + (size_t)b * SEQ * D_MODEL;
    #pragma unroll
    for (int nt = 0; nt < 8; nt++) {
        *(half2*)(Ob + (size_t)row0 * D_MODEL + col + nt * 8) =
            __floats2half2_rn(o[nt][0] * inv0, o[nt][1] * inv0);
        *(half2*)(Ob + (size_t)(row0 + 8) * D_MODEL + col + nt * 8) =
            __floats2half2_rn(o[nt][2] * inv1, o[nt][3] * inv1);
    }
}

// ======================================================================
extern "C" void kernel_launch(void* const* d_in, const int* in_sizes, int n_in,
                              void* d_out, int out_size)
{
    (void)in_sizes; (void)n_in; (void)out_size;
    const float* Q_in = (const float*)d_in[0];
    const float* K_in = (const float*)d_in[1];
    const float* V_in = (const float*)d_in[2];
    const float* W_q  = (const float*)d_in[3];
    const float* W_k  = (const float*)d_in[4];
    const float* W_v  = (const float*)d_in[5];
    const float* W_o  = (const float*)d_in[6];
    float* out = (float*)d_out;

    __half *Qp, *Kp, *Vp, *Ct, *rQ, *rK, *rV, *rWq, *rWk, *rWv, *rWo;
    cudaGetSymbolAddress((void**)&Qp, g_Qp);
    cudaGetSymbolAddress((void**)&Kp, g_Kp);
    cudaGetSymbolAddress((void**)&Vp, g_Vp);
    cudaGetSymbolAddress((void**)&Ct, g_Ct);
    cudaGetSymbolAddress((void**)&rQ, g_rQ);
    cudaGetSymbolAddress((void**)&rK, g_rK);
    cudaGetSymbolAddress((void**)&rV, g_rV);
    cudaGetSymbolAddress((void**)&rWq, g_rWq);
    cudaGetSymbolAddress((void**)&rWk, g_rWk);
    cudaGetSymbolAddress((void**)&rWv, g_rWv);
    cudaGetSymbolAddress((void**)&rWo, g_rWo);

    cudaFuncSetAttribute(gemm_qkv, cudaFuncAttributeMaxDynamicSharedMemorySize, GEMM_SMEM);
    cudaFuncSetAttribute(gemm_tc, cudaFuncAttributeMaxDynamicSharedMemorySize, GEMM_SMEM);
    cudaFuncSetAttribute(flash_tc, cudaFuncAttributeMaxDynamicSharedMemorySize, FLASH_SMEM);

    round_all<<<(NTOT4 + 255) / 256, 256>>>(Q_in, K_in, V_in, W_q, W_k, W_v, W_o,
                                            rQ, rK, rV, rWq, rWk, rWv, rWo);

    gemm_qkv<<<dim3(8, 64, 3), 256, GEMM_SMEM>>>(rQ, rK, rV, rWq, rWk, rWv, Qp, Kp, Vp);

    flash_tc<<<dim3(SEQ / 128, NHEAD, BATCH), 256, FLASH_SMEM>>>(Qp, Kp, Vp, Ct);

    gemm_tc<<<dim3(8, 64), 256, GEMM_SMEM>>>(Ct, rWo, out, 0);
}

// round 14
// speedup vs baseline: 1.4863x; 1.4863x over previous
#include <cuda_runtime.h>
#include <cuda_fp16.h>
#include <cstdint>

#define D_MODEL 1024
#define NHEAD   16
#define DKH     64
#define BATCH   4
#define SEQ     2048
#define MTOT    (BATCH*SEQ)   // 8192

// Scratch: projected Q/K/V + attention concat in fp16, all [b][s][h*d].
__device__ __half g_Qp[(size_t)MTOT * D_MODEL];
__device__ __half g_Kp[(size_t)MTOT * D_MODEL];
__device__ __half g_Vp[(size_t)MTOT * D_MODEL];
__device__ __half g_Ct[(size_t)MTOT * D_MODEL];
// fp16-RN pre-rounded copies (cp.async path cannot convert)
__device__ __half g_rQ[(size_t)MTOT * D_MODEL];
__device__ __half g_rK[(size_t)MTOT * D_MODEL];
__device__ __half g_rV[(size_t)MTOT * D_MODEL];
__device__ __half g_rWq[(size_t)D_MODEL * D_MODEL];
__device__ __half g_rWk[(size_t)D_MODEL * D_MODEL];
__device__ __half g_rWv[(size_t)D_MODEL * D_MODEL];
__device__ __half g_rWo[(size_t)D_MODEL * D_MODEL];

// ---------------- PTX helpers ----------------
__device__ __forceinline__ float ex2f(float x) {
    float y;
    asm("ex2.approx.f32 %0, %1;" : "=f"(y) : "f"(x));
    return y;
}
__device__ __forceinline__ uint32_t smem_u32(const void* p) {
    uint32_t a;
    asm("{ .reg .u64 t; cvta.to.shared.u64 t, %1; cvt.u32.u64 %0, t; }" : "=r"(a) : "l"(p));
    return a;
}
__device__ __forceinline__ void mma_f16(float c[4], const uint32_t a[4],
                                        uint32_t b0, uint32_t b1) {
    asm volatile(
        "mma.sync.aligned.m16n8k16.row.col.f32.f16.f16.f32 "
        "{%0,%1,%2,%3}, {%4,%5,%6,%7}, {%8,%9}, {%0,%1,%2,%3};"
        : "+f"(c[0]), "+f"(c[1]), "+f"(c[2]), "+f"(c[3])
        : "r"(a[0]), "r"(a[1]), "r"(a[2]), "r"(a[3]), "r"(b0), "r"(b1));
}
#define LDSM_X4(r0,r1,r2,r3,addr) \
    asm volatile("ldmatrix.sync.aligned.m8n8.x4.shared.b16 {%0,%1,%2,%3}, [%4];" \
        : "=r"(r0),"=r"(r1),"=r"(r2),"=r"(r3) : "r"(addr))
#define LDSM_X4_T(r0,r1,r2,r3,addr) \
    asm volatile("ldmatrix.sync.aligned.m8n8.x4.trans.shared.b16 {%0,%1,%2,%3}, [%4];" \
        : "=r"(r0),"=r"(r1),"=r"(r2),"=r"(r3) : "r"(addr))
#define CP16(sa, ga)  asm volatile("cp.async.cg.shared.global [%0], [%1], 16;" :: "r"(sa), "l"(ga))
#define CP_COMMIT()   asm volatile("cp.async.commit_group;" ::: "memory")
#define CP_WAIT(n)    asm volatile("cp.async.wait_group %0;" :: "n"(n) : "memory")

// ---------------- fused fp16-RN rounding pass ----------------
#define NB4 (MTOT * D_MODEL / 4)
#define NW4 (D_MODEL * D_MODEL / 4)
#define NTOT4 (3 * NB4 + 4 * NW4)

__global__ void round_all(
    const float* __restrict__ Qi, const float* __restrict__ Ki, const float* __restrict__ Vi,
    const float* __restrict__ Wq, const float* __restrict__ Wk,
    const float* __restrict__ Wv, const float* __restrict__ Wo,
    __half* __restrict__ rQ, __half* __restrict__ rK, __half* __restrict__ rV,
    __half* __restrict__ rWq, __half* __restrict__ rWk, __half* __restrict__ rWv,
    __half* __restrict__ rWo)
{
    const int i = blockIdx.x * blockDim.x + threadIdx.x;
    if (i >= NTOT4) return;
    const float4* src;
    __half* dst;
    int off;
    if (i < 3 * NB4) {
        const int seg = i / NB4;
        off = i - seg * NB4;
        src = (const float4*)(seg == 0 ? Qi : seg == 1 ? Ki : Vi);
        dst = seg == 0 ? rQ : seg == 1 ? rK : rV;
    } else {
        const int j = i - 3 * NB4;
        const int seg = j / NW4;
        off = j - seg * NW4;
        src = (const float4*)(seg == 0 ? Wq : seg == 1 ? Wk : seg == 2 ? Wv : Wo);
        dst = seg == 0 ? rWq : seg == 1 ? rWk : seg == 2 ? rWv : rWo;
    }
    float4 v = src[off];
    half2 h0 = __floats2half2_rn(v.x, v.y);
    half2 h1 = __floats2half2_rn(v.z, v.w);
    uint2 u;
    u.x = *(uint32_t*)&h0;
    u.y = *(uint32_t*)&h1;
    *(uint2*)(dst + 4 * (size_t)off) = u;
}

// ======================================================================
// fp16 GEMM core (NT): C[8192,1024] = A * B^T. 128x128 tile, BK=64
// (128B rows), 3-stage cp.async, ldmatrix, m16n8k16 MMA.
// mode 0: raw fp32 out. mode 1: fp16 out.
// ======================================================================
#define GEMM_SMEM (3 * 32768)

__device__ __forceinline__ void gemm_body(
    const __half* __restrict__ A, const __half* __restrict__ B,
    void* __restrict__ Cv, int mode, char* sm)
{
    const uint32_t sbase = smem_u32(sm);
    const int tid = threadIdx.x, lane = tid & 31, wid = tid >> 5;
    const int wm = (wid & 1) * 64, wn = (wid >> 1) * 32;
    const int m0 = blockIdx.y * 128, n0 = blockIdx.x * 128;

    float c[4][4][4];
    #pragma unroll
    for (int i = 0; i < 4; i++)
        #pragma unroll
        for (int j = 0; j < 4; j++)
            #pragma unroll
            for (int r = 0; r < 4; r++) c[i][j][r] = 0.f;

    auto issue = [&](int kt, int buf) {
        #pragma unroll
        for (int i = 0; i < 4; i++) {
            const int id = tid + 256 * i;
            const int row = id >> 3, cx = id & 7;
            const uint32_t off = row * 128 + (((uint32_t)(cx ^ (row & 7))) << 4);
            const __half* ga = A + (size_t)(m0 + row) * 1024 + kt * 64 + cx * 8;
            const __half* gb = B + (size_t)(n0 + row) * 1024 + kt * 64 + cx * 8;
            CP16(sbase + buf * 32768 + off, ga);
            CP16(sbase + buf * 32768 + 16384 + off, gb);
        }
        CP_COMMIT();
    };

    issue(0, 0);
    issue(1, 1);

    const int NKT = 16;
    for (int kt = 0; kt < NKT; kt++) {
        if (kt + 1 < NKT) { CP_WAIT(1); } else { CP_WAIT(0); }
        __syncthreads();
        if (kt + 2 < NKT) issue(kt + 2, (kt + 2) % 3);

        const uint32_t abase = sbase + (kt % 3) * 32768;
        const uint32_t bbase = abase + 16384;
        #pragma unroll
        for (int ks = 0; ks < 4; ks++) {
            uint32_t a[4][4];
            #pragma unroll
            for (int mt = 0; mt < 4; mt++) {
                const int row = wm + mt * 16 + (lane & 7) + ((lane >> 3) & 1) * 8;
                const int ch  = 2 * ks + (lane >> 4);
                const uint32_t ad = abase + row * 128 + (((uint32_t)(ch ^ (row & 7))) << 4);
                LDSM_X4(a[mt][0], a[mt][1], a[mt][2], a[mt][3], ad);
            }
            #pragma unroll
            for (int p = 0; p < 2; p++) {
                const int row = wn + p * 16 + ((lane >> 4) & 1) * 8 + (lane & 7);
                const int ch  = 2 * ks + ((lane >> 3) & 1);
                const uint32_t bd = bbase + row * 128 + (((uint32_t)(ch ^ (row & 7))) << 4);
                uint32_t b0, b1, b2, b3;
                LDSM_X4(b0, b1, b2, b3, bd);
                #pragma unroll
                for (int mt = 0; mt < 4; mt++) {
                    mma_f16(c[mt][2*p],     a[mt], b0, b1);
                    mma_f16(c[mt][2*p + 1], a[mt], b2, b3);
                }
            }
        }
    }

    const int mbase = m0 + wm + (lane >> 2);
    const int nbase = n0 + wn + (lane & 3) * 2;
    if (mode == 1) {
        __half* Ch = (__half*)Cv;
        #pragma unroll
        for (int mt = 0; mt < 4; mt++) {
            #pragma unroll
            for (int nt = 0; nt < 4; nt++) {
                *(half2*)(Ch + (size_t)(mbase + mt*16)     * 1024 + nbase + nt*8) =
                    __floats2half2_rn(c[mt][nt][0], c[mt][nt][1]);
                *(half2*)(Ch + (size_t)(mbase + mt*16 + 8) * 1024 + nbase + nt*8) =
                    __floats2half2_rn(c[mt][nt][2], c[mt][nt][3]);
            }
        }
    } else {
        float* C = (float*)Cv;
        #pragma unroll
        for (int mt = 0; mt < 4; mt++) {
            #pragma unroll
            for (int nt = 0; nt < 4; nt++) {
                float* p0 = C + (size_t)(mbase + mt*16)     * 1024 + nbase + nt*8;
                float* p1 = C + (size_t)(mbase + mt*16 + 8) * 1024 + nbase + nt*8;
                *(float2*)p0 = make_float2(c[mt][nt][0], c[mt][nt][1]);
                *(float2*)p1 = make_float2(c[mt][nt][2], c[mt][nt][3]);
            }
        }
    }
}

// Fused QKV projections: blockIdx.z selects (A, B, C).
__global__ __launch_bounds__(256, 2) void gemm_qkv(
    const __half* __restrict__ A0, const __half* __restrict__ A1, const __half* __restrict__ A2,
    const __half* __restrict__ B0, const __half* __restrict__ B1, const __half* __restrict__ B2,
    __half* __restrict__ C0, __half* __restrict__ C1, __half* __restrict__ C2)
{
    extern __shared__ char sm[];
    const int z = blockIdx.z;
    const __half* A = z == 0 ? A0 : z == 1 ? A1 : A2;
    const __half* B = z == 0 ? B0 : z == 1 ? B1 : B2;
    __half* C       = z == 0 ? C0 : z == 1 ? C1 : C2;
    gemm_body(A, B, C, 1, sm);
}

__global__ __launch_bounds__(256, 2) void gemm_tc(
    const __half* __restrict__ A, const __half* __restrict__ B,
    float* __restrict__ C, int mode)
{
    extern __shared__ char sm[];
    gemm_body(A, B, C, mode, sm);
}

// ======================================================================
// Flash attention v7 (fp16 MMA m16n8k16, fp32 softmax/accum).
// BQ=128, 8 warps/CTA, 2 CTAs/SM (48 KB smem). K/V double-buffered via
// cp.async, end-of-iteration prefetch. P fp16 overlays Q staging.
// Smem: K0 8K | K1 8K | V0 8K | V1 8K | PQ 16K = 48 KB.
// ======================================================================
#define KOFF(buf)  ((buf) * 8192)
#define VOFF(buf)  (16384 + (buf) * 8192)
#define POFF       32768
#define FLASH_SMEM 49152
#define SM_SCALE_LOG2E 0.1803368801111204f   // 0.125 * log2(e)

__global__ __launch_bounds__(256, 2) void flash_tc(
    const __half* __restrict__ Qp, const __half* __restrict__ Kp,
    const __half* __restrict__ Vp, __half* __restrict__ Op)
{
    extern __shared__ char fsc[];
    const uint32_t sb = smem_u32(fsc);
    const int tid = threadIdx.x, lane = tid & 31, w = tid >> 5;
    const int b = blockIdx.z, h = blockIdx.y;
    const int q0 = blockIdx.x * 128;

    const __half* Qg = Qp + ((size_t)b * SEQ + q0) * D_MODEL + h * DKH;
    const __half* Kg = Kp + (size_t)b * SEQ * D_MODEL + h * DKH;
    const __half* Vg = Vp + (size_t)b * SEQ * D_MODEL + h * DKH;

    auto issueKV = [&](int kt, int buf) {
        #pragma unroll
        for (int i = 0; i < 2; i++) {
            const int id = tid + 256 * i;
            const int row = id >> 3, cx = id & 7;
            const uint32_t off = row * 128 + (((uint32_t)(cx ^ (row & 7))) << 4);
            CP16(sb + KOFF(buf) + off, Kg + (size_t)(kt * 64 + row) * D_MODEL + cx * 8);
            CP16(sb + VOFF(buf) + off, Vg + (size_t)(kt * 64 + row) * D_MODEL + cx * 8);
        }
        CP_COMMIT();
    };

    #pragma unroll
    for (int i = 0; i < 4; i++) {
        const int id = tid + 256 * i;
        const int row = id >> 3, cx = id & 7;
        const uint32_t off = row * 128 + (((uint32_t)(cx ^ (row & 7))) << 4);
        CP16(sb + POFF + off, Qg + (size_t)row * D_MODEL + cx * 8);
    }
    issueKV(0, 0);
    issueKV(1, 1);

    float o[8][4];
    #pragma unroll
    for (int nt = 0; nt < 8; nt++)
        #pragma unroll
        for (int j = 0; j < 4; j++) o[nt][j] = 0.f;
    float m0r = -1e30f, m1r = -1e30f, l0r = 0.f, l1r = 0.f;
    uint32_t qf[4][4];

    const int arow = w * 16 + (lane & 7) + ((lane >> 3) & 1) * 8;
    const uint32_t arow_off = (uint32_t)arow * 128;
    const int asw = arow & 7;
    const int achsel = lane >> 4;

    const int NKT = SEQ / 64;
    for (int kt = 0; kt < NKT; kt++) {
        if (kt + 1 < NKT) { CP_WAIT(1); } else { CP_WAIT(0); }
        __syncthreads();

        if (kt == 0) {
            #pragma unroll
            for (int ks = 0; ks < 4; ks++) {
                const uint32_t ad = sb + POFF + arow_off +
                    (((uint32_t)((2 * ks + achsel) ^ asw)) << 4);
                LDSM_X4(qf[ks][0], qf[ks][1], qf[ks][2], qf[ks][3], ad);
            }
        }

        const int buf = kt & 1;
        const uint32_t Kb = sb + KOFF(buf);
        const uint32_t Vb = sb + VOFF(buf);

        float sf[8][4];
        #pragma unroll
        for (int nt = 0; nt < 8; nt++)
            #pragma unroll
            for (int j = 0; j < 4; j++) sf[nt][j] = 0.f;

        #pragma unroll
        for (int ks = 0; ks < 4; ks++) {
            #pragma unroll
            for (int pp = 0; pp < 4; pp++) {
                const int krow = (2 * pp + ((lane >> 4) & 1)) * 8 + (lane & 7);
                const int kch  = 2 * ks + ((lane >> 3) & 1);
                const uint32_t bd = Kb + (uint32_t)krow * 128 +
                    (((uint32_t)(kch ^ (krow & 7))) << 4);
                uint32_t b0, b1, b2, b3;
                LDSM_X4(b0, b1, b2, b3, bd);
                mma_f16(sf[2*pp],     qf[ks], b0, b1);
                mma_f16(sf[2*pp + 1], qf[ks], b2, b3);
            }
        }

        float mn0 = m0r, mn1 = m1r;
        #pragma unroll
        for (int nt = 0; nt < 8; nt++) {
            mn0 = fmaxf(mn0, fmaxf(sf[nt][0], sf[nt][1]));
            mn1 = fmaxf(mn1, fmaxf(sf[nt][2], sf[nt][3]));
        }
        mn0 = fmaxf(mn0, __shfl_xor_sync(0xffffffffu, mn0, 1));
        mn0 = fmaxf(mn0, __shfl_xor_sync(0xffffffffu, mn0, 2));
        mn1 = fmaxf(mn1, __shfl_xor_sync(0xffffffffu, mn1, 1));
        mn1 = fmaxf(mn1, __shfl_xor_sync(0xffffffffu, mn1, 2));
        const float corr0 = ex2f((m0r - mn0) * SM_SCALE_LOG2E);
        const float corr1 = ex2f((m1r - mn1) * SM_SCALE_LOG2E);
        m0r = mn0; m1r = mn1;
        const float nc0 = -mn0 * SM_SCALE_LOG2E;
        const float nc1 = -mn1 * SM_SCALE_LOG2E;

        float rs0 = 0.f, rs1 = 0.f;
        #pragma unroll
        for (int nt = 0; nt < 8; nt++) {
            sf[nt][0] = ex2f(fmaf(sf[nt][0], SM_SCALE_LOG2E, nc0));
            sf[nt][1] = ex2f(fmaf(sf[nt][1], SM_SCALE_LOG2E, nc0));
            sf[nt][2] = ex2f(fmaf(sf[nt][2], SM_SCALE_LOG2E, nc1));
            sf[nt][3] = ex2f(fmaf(sf[nt][3], SM_SCALE_LOG2E, nc1));
            rs0 += sf[nt][0] + sf[nt][1];
            rs1 += sf[nt][2] + sf[nt][3];
        }
        rs0 += __shfl_xor_sync(0xffffffffu, rs0, 1);
        rs0 += __shfl_xor_sync(0xffffffffu, rs0, 2);
        rs1 += __shfl_xor_sync(0xffffffffu, rs1, 1);
        rs1 += __shfl_xor_sync(0xffffffffu, rs1, 2);
        l0r = l0r * corr0 + rs0;
        l1r = l1r * corr1 + rs1;
        #pragma unroll
        for (int nt = 0; nt < 8; nt++) {
            o[nt][0] *= corr0; o[nt][1] *= corr0;
            o[nt][2] *= corr1; o[nt][3] *= corr1;
        }

        {
            const int r0 = w * 16 + (lane >> 2);
            const int r1 = r0 + 8;
            const uint32_t cc4 = (uint32_t)(lane & 3) * 4;
            #pragma unroll
            for (int nt = 0; nt < 8; nt++) {
                *(half2*)(fsc + POFF + r0 * 128 +
                          (((uint32_t)(nt ^ (r0 & 7))) << 4) + cc4) =
                    __floats2half2_rn(sf[nt][0], sf[nt][1]);
                *(half2*)(fsc + POFF + r1 * 128 +
                          (((uint32_t)(nt ^ (r1 & 7))) << 4) + cc4) =
                    __floats2half2_rn(sf[nt][2], sf[nt][3]);
            }
        }
        __syncwarp();

        #pragma unroll
        for (int ks = 0; ks < 4; ks++) {
            uint32_t pf[4];
            const uint32_t pd = sb + POFF + arow_off +
                (((uint32_t)((2 * ks + achsel) ^ asw)) << 4);
            LDSM_X4(pf[0], pf[1], pf[2], pf[3], pd);
            #pragma unroll
            for (int pp = 0; pp < 4; pp++) {
                const int vrow = ks * 16 + (lane & 7) + ((lane >> 3) & 1) * 8;
                const int vch  = 2 * pp + ((lane >> 4) & 1);
                const uint32_t vd = Vb + (uint32_t)vrow * 128 +
                    (((uint32_t)(vch ^ (vrow & 7))) << 4);
                uint32_t b0, b1, b2, b3;
                LDSM_X4_T(b0, b1, b2, b3, vd);
                mma_f16(o[2*pp],     pf, b0, b1);
                mma_f16(o[2*pp + 1], pf, b2, b3);
            }
        }

        if (kt + 2 < NKT) {
            __syncthreads();
            issueKV(kt + 2, buf);
        }
    }

    // epilogue: normalize, fp16-round, write Ct (fp16)
    const float inv0 = 1.f / l0r, inv1 = 1.f / l1r;
    const int row0 = q0 + w * 16 + (lane >> 2);
    const int col  = h * DKH + (lane & 3) * 2;
    __half* Ob = Op + (size_t)b * SEQ * D_MODEL;
    #pragma unroll
    for (int nt = 0; nt < 8; nt++) {
        *(half2*)(Ob + (size_t)row0 * D_MODEL + col + nt * 8) =
            __floats2half2_rn(o[nt][0] * inv0, o[nt][1] * inv0);
        *(half2*)(Ob + (size_t)(row0 + 8) * D_MODEL + col + nt * 8) =
            __floats2half2_rn(o[nt][2] * inv1, o[nt][3] * inv1);
    }
}

// ======================================================================
extern "C" void kernel_launch(void* const* d_in, const int* in_sizes, int n_in,
                              void* d_out, int out_size)
{
    (void)in_sizes; (void)n_in; (void)out_size;
    const float* Q_in = (const float*)d_in[0];
    const float* K_in = (const float*)d_in[1];
    const float* V_in = (const float*)d_in[2];
    const float* W_q  = (const float*)d_in[3];
    const float* W_k  = (const float*)d_in[4];
    const float* W_v  = (const float*)d_in[5];
    const float* W_o  = (const float*)d_in[6];
    float* out = (float*)d_out;

    __half *Qp, *Kp, *Vp, *Ct, *rQ, *rK, *rV, *rWq, *rWk, *rWv, *rWo;
    cudaGetSymbolAddress((void**)&Qp, g_Qp);
    cudaGetSymbolAddress((void**)&Kp, g_Kp);
    cudaGetSymbolAddress((void**)&Vp, g_Vp);
    cudaGetSymbolAddress((void**)&Ct, g_Ct);
    cudaGetSymbolAddress((void**)&rQ, g_rQ);
    cudaGetSymbolAddress((void**)&rK, g_rK);
    cudaGetSymbolAddress((void**)&rV, g_rV);
    cudaGetSymbolAddress((void**)&rWq, g_rWq);
    cudaGetSymbolAddress((void**)&rWk, g_rWk);
    cudaGetSymbolAddress((void**)&rWv, g_rWv);
    cudaGetSymbolAddress((void**)&rWo, g_rWo);

    cudaFuncSetAttribute(gemm_qkv, cudaFuncAttributeMaxDynamicSharedMemorySize, GEMM_SMEM);
    cudaFuncSetAttribute(gemm_tc, cudaFuncAttributeMaxDynamicSharedMemorySize, GEMM_SMEM);
    cudaFuncSetAttribute(flash_tc, cudaFuncAttributeMaxDynamicSharedMemorySize, FLASH_SMEM);

    round_all<<<(NTOT4 + 255) / 256, 256>>>(Q_in, K_in, V_in, W_q, W_k, W_v, W_o,
                                            rQ, rK, rV, rWq, rWk, rWv, rWo);

    gemm_qkv<<<dim3(8, 64, 3), 256, GEMM_SMEM>>>(rQ, rK, rV, rWq, rWk, rWv, Qp, Kp, Vp);

    flash_tc<<<dim3(SEQ / 128, NHEAD, BATCH), 256, FLASH_SMEM>>>(Qp, Kp, Vp, Ct);

    gemm_tc<<<dim3(8, 64), 256, GEMM_SMEM>>>(Ct, rWo, out, 0);
}

// round 15
// speedup vs baseline: 1.5783x; 1.0619x over previous
#include <cuda_runtime.h>
#include <cuda_fp16.h>
#include <cstdint>

#define D_MODEL 1024
#define NHEAD   16
#define DKH     64
#define BATCH   4
#define SEQ     2048
#define MTOT    (BATCH*SEQ)   // 8192

// Scratch: projected Q/K/V + attention concat in fp16, all [b][s][h*d].
__device__ __half g_Qp[(size_t)MTOT * D_MODEL];
__device__ __half g_Kp[(size_t)MTOT * D_MODEL];
__device__ __half g_Vp[(size_t)MTOT * D_MODEL];
__device__ __half g_Ct[(size_t)MTOT * D_MODEL];
// fp16-RN pre-rounded copies (cp.async path cannot convert)
__device__ __half g_rQ[(size_t)MTOT * D_MODEL];
__device__ __half g_rK[(size_t)MTOT * D_MODEL];
__device__ __half g_rV[(size_t)MTOT * D_MODEL];
__device__ __half g_rWq[(size_t)D_MODEL * D_MODEL];
__device__ __half g_rWk[(size_t)D_MODEL * D_MODEL];
__device__ __half g_rWv[(size_t)D_MODEL * D_MODEL];
__device__ __half g_rWo[(size_t)D_MODEL * D_MODEL];

// ---------------- PTX helpers ----------------
__device__ __forceinline__ float ex2f(float x) {
    float y;
    asm("ex2.approx.f32 %0, %1;" : "=f"(y) : "f"(x));
    return y;
}
__device__ __forceinline__ uint32_t smem_u32(const void* p) {
    uint32_t a;
    asm("{ .reg .u64 t; cvta.to.shared.u64 t, %1; cvt.u32.u64 %0, t; }" : "=r"(a) : "l"(p));
    return a;
}
__device__ __forceinline__ void mma_f16(float c[4], const uint32_t a[4],
                                        uint32_t b0, uint32_t b1) {
    asm volatile(
        "mma.sync.aligned.m16n8k16.row.col.f32.f16.f16.f32 "
        "{%0,%1,%2,%3}, {%4,%5,%6,%7}, {%8,%9}, {%0,%1,%2,%3};"
        : "+f"(c[0]), "+f"(c[1]), "+f"(c[2]), "+f"(c[3])
        : "r"(a[0]), "r"(a[1]), "r"(a[2]), "r"(a[3]), "r"(b0), "r"(b1));
}
__device__ __forceinline__ uint32_t pack_h2(float a, float b) {
    half2 h = __floats2half2_rn(a, b);
    return *(uint32_t*)&h;
}
#define LDSM_X4(r0,r1,r2,r3,addr) \
    asm volatile("ldmatrix.sync.aligned.m8n8.x4.shared.b16 {%0,%1,%2,%3}, [%4];" \
        : "=r"(r0),"=r"(r1),"=r"(r2),"=r"(r3) : "r"(addr))
#define LDSM_X4_T(r0,r1,r2,r3,addr) \
    asm volatile("ldmatrix.sync.aligned.m8n8.x4.trans.shared.b16 {%0,%1,%2,%3}, [%4];" \
        : "=r"(r0),"=r"(r1),"=r"(r2),"=r"(r3) : "r"(addr))
#define CP16(sa, ga)  asm volatile("cp.async.cg.shared.global [%0], [%1], 16;" :: "r"(sa), "l"(ga))
#define CP_COMMIT()   asm volatile("cp.async.commit_group;" ::: "memory")
#define CP_WAIT(n)    asm volatile("cp.async.wait_group %0;" :: "n"(n) : "memory")

// ---------------- fused fp16-RN rounding pass ----------------
#define NB4 (MTOT * D_MODEL / 4)
#define NW4 (D_MODEL * D_MODEL / 4)
#define NTOT4 (3 * NB4 + 4 * NW4)

__global__ void round_all(
    const float* __restrict__ Qi, const float* __restrict__ Ki, const float* __restrict__ Vi,
    const float* __restrict__ Wq, const float* __restrict__ Wk,
    const float* __restrict__ Wv, const float* __restrict__ Wo,
    __half* __restrict__ rQ, __half* __restrict__ rK, __half* __restrict__ rV,
    __half* __restrict__ rWq, __half* __restrict__ rWk, __half* __restrict__ rWv,
    __half* __restrict__ rWo)
{
    const int i = blockIdx.x * blockDim.x + threadIdx.x;
    if (i >= NTOT4) return;
    const float4* src;
    __half* dst;
    int off;
    if (i < 3 * NB4) {
        const int seg = i / NB4;
        off = i - seg * NB4;
        src = (const float4*)(seg == 0 ? Qi : seg == 1 ? Ki : Vi);
        dst = seg == 0 ? rQ : seg == 1 ? rK : rV;
    } else {
        const int j = i - 3 * NB4;
        const int seg = j / NW4;
        off = j - seg * NW4;
        src = (const float4*)(seg == 0 ? Wq : seg == 1 ? Wk : seg == 2 ? Wv : Wo);
        dst = seg == 0 ? rWq : seg == 1 ? rWk : seg == 2 ? rWv : rWo;
    }
    float4 v = src[off];
    half2 h0 = __floats2half2_rn(v.x, v.y);
    half2 h1 = __floats2half2_rn(v.z, v.w);
    uint2 u;
    u.x = *(uint32_t*)&h0;
    u.y = *(uint32_t*)&h1;
    *(uint2*)(dst + 4 * (size_t)off) = u;
}

// ======================================================================
// fp16 GEMM core (NT): C[8192,1024] = A * B^T. 128x128 tile, BK=64
// (128B rows), 3-stage cp.async, ldmatrix, m16n8k16 MMA.
// mode 0: raw fp32 out. mode 1: fp16 out.
// ======================================================================
#define GEMM_SMEM (3 * 32768)

__device__ __forceinline__ void gemm_body(
    const __half* __restrict__ A, const __half* __restrict__ B,
    void* __restrict__ Cv, int mode, char* sm)
{
    const uint32_t sbase = smem_u32(sm);
    const int tid = threadIdx.x, lane = tid & 31, wid = tid >> 5;
    const int wm = (wid & 1) * 64, wn = (wid >> 1) * 32;
    const int m0 = blockIdx.y * 128, n0 = blockIdx.x * 128;

    float c[4][4][4];
    #pragma unroll
    for (int i = 0; i < 4; i++)
        #pragma unroll
        for (int j = 0; j < 4; j++)
            #pragma unroll
            for (int r = 0; r < 4; r++) c[i][j][r] = 0.f;

    auto issue = [&](int kt, int buf) {
        #pragma unroll
        for (int i = 0; i < 4; i++) {
            const int id = tid + 256 * i;
            const int row = id >> 3, cx = id & 7;
            const uint32_t off = row * 128 + (((uint32_t)(cx ^ (row & 7))) << 4);
            const __half* ga = A + (size_t)(m0 + row) * 1024 + kt * 64 + cx * 8;
            const __half* gb = B + (size_t)(n0 + row) * 1024 + kt * 64 + cx * 8;
            CP16(sbase + buf * 32768 + off, ga);
            CP16(sbase + buf * 32768 + 16384 + off, gb);
        }
        CP_COMMIT();
    };

    issue(0, 0);
    issue(1, 1);

    const int NKT = 16;
    for (int kt = 0; kt < NKT; kt++) {
        if (kt + 1 < NKT) { CP_WAIT(1); } else { CP_WAIT(0); }
        __syncthreads();
        if (kt + 2 < NKT) issue(kt + 2, (kt + 2) % 3);

        const uint32_t abase = sbase + (kt % 3) * 32768;
        const uint32_t bbase = abase + 16384;
        #pragma unroll
        for (int ks = 0; ks < 4; ks++) {
            uint32_t a[4][4];
            #pragma unroll
            for (int mt = 0; mt < 4; mt++) {
                const int row = wm + mt * 16 + (lane & 7) + ((lane >> 3) & 1) * 8;
                const int ch  = 2 * ks + (lane >> 4);
                const uint32_t ad = abase + row * 128 + (((uint32_t)(ch ^ (row & 7))) << 4);
                LDSM_X4(a[mt][0], a[mt][1], a[mt][2], a[mt][3], ad);
            }
            #pragma unroll
            for (int p = 0; p < 2; p++) {
                const int row = wn + p * 16 + ((lane >> 4) & 1) * 8 + (lane & 7);
                const int ch  = 2 * ks + ((lane >> 3) & 1);
                const uint32_t bd = bbase + row * 128 + (((uint32_t)(ch ^ (row & 7))) << 4);
                uint32_t b0, b1, b2, b3;
                LDSM_X4(b0, b1, b2, b3, bd);
                #pragma unroll
                for (int mt = 0; mt < 4; mt++) {
                    mma_f16(c[mt][2*p],     a[mt], b0, b1);
                    mma_f16(c[mt][2*p + 1], a[mt], b2, b3);
                }
            }
        }
    }

    const int mbase = m0 + wm + (lane >> 2);
    const int nbase = n0 + wn + (lane & 3) * 2;
    if (mode == 1) {
        __half* Ch = (__half*)Cv;
        #pragma unroll
        for (int mt = 0; mt < 4; mt++) {
            #pragma unroll
            for (int nt = 0; nt < 4; nt++) {
                *(half2*)(Ch + (size_t)(mbase + mt*16)     * 1024 + nbase + nt*8) =
                    __floats2half2_rn(c[mt][nt][0], c[mt][nt][1]);
                *(half2*)(Ch + (size_t)(mbase + mt*16 + 8) * 1024 + nbase + nt*8) =
                    __floats2half2_rn(c[mt][nt][2], c[mt][nt][3]);
            }
        }
    } else {
        float* C = (float*)Cv;
        #pragma unroll
        for (int mt = 0; mt < 4; mt++) {
            #pragma unroll
            for (int nt = 0; nt < 4; nt++) {
                float* p0 = C + (size_t)(mbase + mt*16)     * 1024 + nbase + nt*8;
                float* p1 = C + (size_t)(mbase + mt*16 + 8) * 1024 + nbase + nt*8;
                *(float2*)p0 = make_float2(c[mt][nt][0], c[mt][nt][1]);
                *(float2*)p1 = make_float2(c[mt][nt][2], c[mt][nt][3]);
            }
        }
    }
}

// Fused QKV projections: blockIdx.z selects (A, B, C).
__global__ __launch_bounds__(256, 2) void gemm_qkv(
    const __half* __restrict__ A0, const __half* __restrict__ A1, const __half* __restrict__ A2,
    const __half* __restrict__ B0, const __half* __restrict__ B1, const __half* __restrict__ B2,
    __half* __restrict__ C0, __half* __restrict__ C1, __half* __restrict__ C2)
{
    extern __shared__ char sm[];
    const int z = blockIdx.z;
    const __half* A = z == 0 ? A0 : z == 1 ? A1 : A2;
    const __half* B = z == 0 ? B0 : z == 1 ? B1 : B2;
    __half* C       = z == 0 ? C0 : z == 1 ? C1 : C2;
    gemm_body(A, B, C, 1, sm);
}

__global__ __launch_bounds__(256, 2) void gemm_tc(
    const __half* __restrict__ A, const __half* __restrict__ B,
    float* __restrict__ C, int mode)
{
    extern __shared__ char sm[];
    gemm_body(A, B, C, mode, sm);
}

// ======================================================================
// Flash attention v10 (fp16 MMA m16n8k16, fp32 softmax/accum).
// BQ=128, 8 warps/CTA, 2 CTAs/SM (48 KB smem). K/V double-buffered via
// cp.async, end-of-iteration prefetch.
// NEW vs v7: (a) P stays IN REGISTERS — the m16n8 accumulator fragment
// pair (2ks, 2ks+1) packs directly into the m16n8k16 A-operand fragment
// (bit-identical to the old smem round-trip); (b) ballot-uniform rescale
// skip when no row max in the warp changed (corr == 1 exactly).
// Smem: K0 8K | K1 8K | V0 8K | V1 8K | Q-staging 16K = 48 KB.
// ======================================================================
#define KOFF(buf)  ((buf) * 8192)
#define VOFF(buf)  (16384 + (buf) * 8192)
#define POFF       32768
#define FLASH_SMEM 49152
#define SM_SCALE_LOG2E 0.1803368801111204f   // 0.125 * log2(e)

__global__ __launch_bounds__(256, 2) void flash_tc(
    const __half* __restrict__ Qp, const __half* __restrict__ Kp,
    const __half* __restrict__ Vp, __half* __restrict__ Op)
{
    extern __shared__ char fsc[];
    const uint32_t sb = smem_u32(fsc);
    const int tid = threadIdx.x, lane = tid & 31, w = tid >> 5;
    const int b = blockIdx.z, h = blockIdx.y;
    const int q0 = blockIdx.x * 128;

    const __half* Qg = Qp + ((size_t)b * SEQ + q0) * D_MODEL + h * DKH;
    const __half* Kg = Kp + (size_t)b * SEQ * D_MODEL + h * DKH;
    const __half* Vg = Vp + (size_t)b * SEQ * D_MODEL + h * DKH;

    auto issueKV = [&](int kt, int buf) {
        #pragma unroll
        for (int i = 0; i < 2; i++) {
            const int id = tid + 256 * i;
            const int row = id >> 3, cx = id & 7;
            const uint32_t off = row * 128 + (((uint32_t)(cx ^ (row & 7))) << 4);
            CP16(sb + KOFF(buf) + off, Kg + (size_t)(kt * 64 + row) * D_MODEL + cx * 8);
            CP16(sb + VOFF(buf) + off, Vg + (size_t)(kt * 64 + row) * D_MODEL + cx * 8);
        }
        CP_COMMIT();
    };

    #pragma unroll
    for (int i = 0; i < 4; i++) {
        const int id = tid + 256 * i;
        const int row = id >> 3, cx = id & 7;
        const uint32_t off = row * 128 + (((uint32_t)(cx ^ (row & 7))) << 4);
        CP16(sb + POFF + off, Qg + (size_t)row * D_MODEL + cx * 8);
    }
    issueKV(0, 0);
    issueKV(1, 1);

    float o[8][4];
    #pragma unroll
    for (int nt = 0; nt < 8; nt++)
        #pragma unroll
        for (int j = 0; j < 4; j++) o[nt][j] = 0.f;
    float m0r = -1e30f, m1r = -1e30f, l0r = 0.f, l1r = 0.f;
    uint32_t qf[4][4];

    const int arow = w * 16 + (lane & 7) + ((lane >> 3) & 1) * 8;
    const uint32_t arow_off = (uint32_t)arow * 128;
    const int asw = arow & 7;
    const int achsel = lane >> 4;

    const int NKT = SEQ / 64;
    for (int kt = 0; kt < NKT; kt++) {
        if (kt + 1 < NKT) { CP_WAIT(1); } else { CP_WAIT(0); }
        __syncthreads();

        if (kt == 0) {   // hoist Q fragments from staging (used all iterations)
            #pragma unroll
            for (int ks = 0; ks < 4; ks++) {
                const uint32_t ad = sb + POFF + arow_off +
                    (((uint32_t)((2 * ks + achsel) ^ asw)) << 4);
                LDSM_X4(qf[ks][0], qf[ks][1], qf[ks][2], qf[ks][3], ad);
            }
        }

        const int buf = kt & 1;
        const uint32_t Kb = sb + KOFF(buf);
        const uint32_t Vb = sb + VOFF(buf);

        // ---- S = Q K^T ----
        float sf[8][4];
        #pragma unroll
        for (int nt = 0; nt < 8; nt++)
            #pragma unroll
            for (int j = 0; j < 4; j++) sf[nt][j] = 0.f;

        #pragma unroll
        for (int ks = 0; ks < 4; ks++) {
            #pragma unroll
            for (int pp = 0; pp < 4; pp++) {
                const int krow = (2 * pp + ((lane >> 4) & 1)) * 8 + (lane & 7);
                const int kch  = 2 * ks + ((lane >> 3) & 1);
                const uint32_t bd = Kb + (uint32_t)krow * 128 +
                    (((uint32_t)(kch ^ (krow & 7))) << 4);
                uint32_t b0, b1, b2, b3;
                LDSM_X4(b0, b1, b2, b3, bd);
                mma_f16(sf[2*pp],     qf[ks], b0, b1);
                mma_f16(sf[2*pp + 1], qf[ks], b2, b3);
            }
        }

        // ---- online softmax ----
        float mn0 = m0r, mn1 = m1r;
        #pragma unroll
        for (int nt = 0; nt < 8; nt++) {
            mn0 = fmaxf(mn0, fmaxf(sf[nt][0], sf[nt][1]));
            mn1 = fmaxf(mn1, fmaxf(sf[nt][2], sf[nt][3]));
        }
        mn0 = fmaxf(mn0, __shfl_xor_sync(0xffffffffu, mn0, 1));
        mn0 = fmaxf(mn0, __shfl_xor_sync(0xffffffffu, mn0, 2));
        mn1 = fmaxf(mn1, __shfl_xor_sync(0xffffffffu, mn1, 1));
        mn1 = fmaxf(mn1, __shfl_xor_sync(0xffffffffu, mn1, 2));

        const bool changed = (mn0 != m0r) || (mn1 != m1r);
        const float nc0 = -mn0 * SM_SCALE_LOG2E;
        const float nc1 = -mn1 * SM_SCALE_LOG2E;

        float rs0 = 0.f, rs1 = 0.f;
        #pragma unroll
        for (int nt = 0; nt < 8; nt++) {
            sf[nt][0] = ex2f(fmaf(sf[nt][0], SM_SCALE_LOG2E, nc0));
            sf[nt][1] = ex2f(fmaf(sf[nt][1], SM_SCALE_LOG2E, nc0));
            sf[nt][2] = ex2f(fmaf(sf[nt][2], SM_SCALE_LOG2E, nc1));
            sf[nt][3] = ex2f(fmaf(sf[nt][3], SM_SCALE_LOG2E, nc1));
            rs0 += sf[nt][0] + sf[nt][1];
            rs1 += sf[nt][2] + sf[nt][3];
        }
        rs0 += __shfl_xor_sync(0xffffffffu, rs0, 1);
        rs0 += __shfl_xor_sync(0xffffffffu, rs0, 2);
        rs1 += __shfl_xor_sync(0xffffffffu, rs1, 1);
        rs1 += __shfl_xor_sync(0xffffffffu, rs1, 2);

        if (__ballot_sync(0xffffffffu, changed)) {
            const float corr0 = ex2f((m0r - mn0) * SM_SCALE_LOG2E);
            const float corr1 = ex2f((m1r - mn1) * SM_SCALE_LOG2E);
            m0r = mn0; m1r = mn1;
            l0r = l0r * corr0 + rs0;
            l1r = l1r * corr1 + rs1;
            #pragma unroll
            for (int nt = 0; nt < 8; nt++) {
                o[nt][0] *= corr0; o[nt][1] *= corr0;
                o[nt][2] *= corr1; o[nt][3] *= corr1;
            }
        } else {
            // no row max changed anywhere in the warp: corr == 1 exactly
            l0r += rs0;
            l1r += rs1;
        }

        // ---- O += P V : P packed in-register into A-fragment layout ----
        // (accumulator tiles 2ks / 2ks+1 are the k8 halves of the k16 A-frag)
        #pragma unroll
        for (int ks = 0; ks < 4; ks++) {
            uint32_t pf[4];
            pf[0] = pack_h2(sf[2*ks][0],     sf[2*ks][1]);
            pf[1] = pack_h2(sf[2*ks][2],     sf[2*ks][3]);
            pf[2] = pack_h2(sf[2*ks+1][0],   sf[2*ks+1][1]);
            pf[3] = pack_h2(sf[2*ks+1][2],   sf[2*ks+1][3]);
            #pragma unroll
            for (int pp = 0; pp < 4; pp++) {
                const int vrow = ks * 16 + (lane & 7) + ((lane >> 3) & 1) * 8;
                const int vch  = 2 * pp + ((lane >> 4) & 1);
                const uint32_t vd = Vb + (uint32_t)vrow * 128 +
                    (((uint32_t)(vch ^ (vrow & 7))) << 4);
                uint32_t b0, b1, b2, b3;
                LDSM_X4_T(b0, b1, b2, b3, vd);
                mma_f16(o[2*pp],     pf, b0, b1);
                mma_f16(o[2*pp + 1], pf, b2, b3);
            }
        }

        if (kt + 2 < NKT) {
            __syncthreads();
            issueKV(kt + 2, buf);
        }
    }

    // epilogue: normalize, fp16-round, write Ct (fp16)
    const float inv0 = 1.f / l0r, inv1 = 1.f / l1r;
    const int row0 = q0 + w * 16 + (lane >> 2);
    const int col  = h * DKH + (lane & 3) * 2;
    __half* Ob = Op + (size_t)b * SEQ * D_MODEL;
    #pragma unroll
    for (int nt = 0; nt < 8; nt++) {
        *(half2*)(Ob + (size_t)row0 * D_MODEL + col + nt * 8) =
            __floats2half2_rn(o[nt][0] * inv0, o[nt][1] * inv0);
        *(half2*)(Ob + (size_t)(row0 + 8) * D_MODEL + col + nt * 8) =
            __floats2half2_rn(o[nt][2] * inv1, o[nt][3] * inv1);
    }
}

// ======================================================================
extern "C" void kernel_launch(void* const* d_in, const int* in_sizes, int n_in,
                              void* d_out, int out_size)
{
    (void)in_sizes; (void)n_in; (void)out_size;
    const float* Q_in = (const float*)d_in[0];
    const float* K_in = (const float*)d_in[1];
    const float* V_in = (const float*)d_in[2];
    const float* W_q  = (const float*)d_in[3];
    const float* W_k  = (const float*)d_in[4];
    const float* W_v  = (const float*)d_in[5];
    const float* W_o  = (const float*)d_in[6];
    float* out = (float*)d_out;

    __half *Qp, *Kp, *Vp, *Ct, *rQ, *rK, *rV, *rWq, *rWk, *rWv, *rWo;
    cudaGetSymbolAddress((void**)&Qp, g_Qp);
    cudaGetSymbolAddress((void**)&Kp, g_Kp);
    cudaGetSymbolAddress((void**)&Vp, g_Vp);
    cudaGetSymbolAddress((void**)&Ct, g_Ct);
    cudaGetSymbolAddress((void**)&rQ, g_rQ);
    cudaGetSymbolAddress((void**)&rK, g_rK);
    cudaGetSymbolAddress((void**)&rV, g_rV);
    cudaGetSymbolAddress((void**)&rWq, g_rWq);
    cudaGetSymbolAddress((void**)&rWk, g_rWk);
    cudaGetSymbolAddress((void**)&rWv, g_rWv);
    cudaGetSymbolAddress((void**)&rWo, g_rWo);

    cudaFuncSetAttribute(gemm_qkv, cudaFuncAttributeMaxDynamicSharedMemorySize, GEMM_SMEM);
    cudaFuncSetAttribute(gemm_tc, cudaFuncAttributeMaxDynamicSharedMemorySize, GEMM_SMEM);
    cudaFuncSetAttribute(flash_tc, cudaFuncAttributeMaxDynamicSharedMemorySize, FLASH_SMEM);

    round_all<<<(NTOT4 + 255) / 256, 256>>>(Q_in, K_in, V_in, W_q, W_k, W_v, W_o,
                                            rQ, rK, rV, rWq, rWk, rWv, rWo);

    gemm_qkv<<<dim3(8, 64, 3), 256, GEMM_SMEM>>>(rQ, rK, rV, rWq, rWk, rWv, Qp, Kp, Vp);

    flash_tc<<<dim3(SEQ / 128, NHEAD, BATCH), 256, FLASH_SMEM>>>(Qp, Kp, Vp, Ct);

    gemm_tc<<<dim3(8, 64), 256, GEMM_SMEM>>>(Ct, rWo, out, 0);
}